// round 15
// baseline (speedup 1.0000x reference)
#include <cuda_runtime.h>
#include <math_constants.h>
#include <stdint.h>

// PQHead: out[b, m*6+d] = codebooks[m, argmax_k <x[b,m*6:...], cb[m,k,:]>, d]
// (forward value of the straight-through estimator == discrete codeword)
//
// FROZEN NUMERICS: dot = x0*c0 then fma.rn chain d=1..5 (scalar FFMA), argmax
// exact, FIRST-max tie rule. Tolerance calibration: ~2 argmax flips total
// breach 1e-3 -> tf32/3xtf32/tensor cores mathematically excluded.
//
// LESSONS: R3/R4 spills; R7 f32x2 half-rate; R12 cp.async; R13 LDS.128 law
// (smem wf are lane-slot based: cb costs 6/RPT wf per pair, layout-invariant).
// Family converged: ~10.5 issues/pair, issue% in [62,69] -> 63-67us.
// R15 = R9 (best issue%, 69.2%) + k0 peel + L1-prefetch assist for the
// register prefetch stream.

#define B_ROWS   32768
#define M_SUB    128
#define QM       16                      // m's per block (1/8 split)
#define NGRP     (M_SUB / QM)            // 8
#define K_CODES  32
#define D_SUB    6
#define DIM      768
#define RPT      2                       // rows per thread
#define TPB      256                     // 16 row-groups x 16 m
#define TILE_ROWS (RPT * (TPB / QM))     // 32
#define NTILES   (B_ROWS / TILE_ROWS)    // 1024 per group
#define BLK_PER_G 74                     // 8 groups x 74 = 592 = 4/SM
#define NBLOCKS  (NGRP * BLK_PER_G)

__global__ void __launch_bounds__(TPB, 4)
pq_head_kernel(const float* __restrict__ x,
               const float* __restrict__ cb,
               float* __restrict__ out)
{
    // Codebook split: cbA[k*16+m] = (d0,d1,d2,d3), cbB[k*16+m] = (d4,d5).
    __shared__ float4 cbA[K_CODES * QM];     // 8KB
    __shared__ float2 cbB[K_CODES * QM];     // 4KB

    const int t = threadIdx.x;
    const int grp = blockIdx.x / BLK_PER_G;      // which m-group this block owns
    const int bstart = blockIdx.x % BLK_PER_G;

    // One-time codebook load for this group.
    {
        const float* cbg = cb + (size_t)grp * QM * (K_CODES * D_SUB);
        for (int i = t; i < QM * K_CODES; i += TPB) {
            int mloc = i / K_CODES;
            int k    = i - mloc * K_CODES;
            const float* src = cbg + (size_t)mloc * (K_CODES * D_SUB) + k * D_SUB;
            cbA[k * QM + mloc] = make_float4(src[0], src[1], src[2], src[3]);
            cbB[k * QM + mloc] = make_float2(src[4], src[5]);
        }
    }
    __syncthreads();

    const int mloc = t & (QM - 1);
    const int g    = t >> 4;             // row-group 0..15
    const int col0 = (grp * QM + mloc) * D_SUB;

    const size_t step = (size_t)BLK_PER_G * TILE_ROWS * DIM;
    const float* xp = x   + (size_t)(bstart * TILE_ROWS + g * RPT) * DIM + col0;
    float*       op = out + (size_t)(bstart * TILE_ROWS + g * RPT) * DIM + col0;

    // Prologue: load first tile's subvectors.
    float xv[RPT][D_SUB];
    #pragma unroll
    for (int r = 0; r < RPT; r++) {
        const float2* p = reinterpret_cast<const float2*>(xp + (size_t)r * DIM);
        float2 a = p[0], bq = p[1], c = p[2];
        xv[r][0] = a.x;  xv[r][1] = a.y;
        xv[r][2] = bq.x; xv[r][3] = bq.y;
        xv[r][4] = c.x;  xv[r][5] = c.y;
    }

    for (int tile = bstart; tile < NTILES; tile += BLK_PER_G) {
        // ---- L1 assist: touch tile+2's lines so the NEXT register prefetch
        // hits L1 (~40cyc) instead of DRAM (~577cyc).
        if (tile + 2 * BLK_PER_G < NTILES) {
            const float* pp = xp + 2 * step;
            #pragma unroll
            for (int r = 0; r < RPT; r++)
                asm volatile("prefetch.global.L1 [%0];"
                             :: "l"(pp + (size_t)r * DIM));
        }

        // ---- Register prefetch of next tile's x (clamped on last tile).
        const float* nxp = (tile + BLK_PER_G < NTILES) ? (xp + step) : xp;
        float nx[RPT][D_SUB];
        #pragma unroll
        for (int r = 0; r < RPT; r++) {
            const float2* p = reinterpret_cast<const float2*>(nxp + (size_t)r * DIM);
            float2 a = p[0], bq = p[1], c = p[2];
            nx[r][0] = a.x;  nx[r][1] = a.y;
            nx[r][2] = bq.x; nx[r][3] = bq.y;
            nx[r][4] = c.x;  nx[r][5] = c.y;
        }

        // ---- k = 0 peeled: best = dot, idx = 0 (dot > -INF always).
        float best[RPT];
        int   idx[RPT];
        {
            const float4 ca  = cbA[mloc];
            const float2 cbv = cbB[mloc];
            #pragma unroll
            for (int r = 0; r < RPT; r++) {
                float dot = xv[r][0] * ca.x;
                dot = fmaf(xv[r][1], ca.y, dot);
                dot = fmaf(xv[r][2], ca.z, dot);
                dot = fmaf(xv[r][3], ca.w, dot);
                dot = fmaf(xv[r][4], cbv.x, dot);
                dot = fmaf(xv[r][5], cbv.y, dot);
                best[r] = dot;
                idx[r]  = 0;
            }
        }

        // ---- k = 1..31 (bounded unroll keeps live set under the 64-reg cap).
        #pragma unroll 4
        for (int k = 1; k < K_CODES; k++) {
            const float4 ca  = cbA[k * QM + mloc];
            const float2 cbv = cbB[k * QM + mloc];
            #pragma unroll
            for (int r = 0; r < RPT; r++) {
                float dot = xv[r][0] * ca.x;
                dot = fmaf(xv[r][1], ca.y, dot);
                dot = fmaf(xv[r][2], ca.z, dot);
                dot = fmaf(xv[r][3], ca.w, dot);
                dot = fmaf(xv[r][4], cbv.x, dot);
                dot = fmaf(xv[r][5], cbv.y, dot);
                // EXACT argmax, FIRST-max tie rule; FMNMX value chain keeps
                // the 13-cyc predicate latency off the loop-carried path.
                bool p  = dot > best[r];
                best[r] = fmaxf(best[r], dot);
                idx[r]  = p ? k : idx[r];
            }
        }

        // ---- Emit the winning codeword rows.
        #pragma unroll
        for (int r = 0; r < RPT; r++) {
            const float4 oa = cbA[idx[r] * QM + mloc];
            const float2 ob = cbB[idx[r] * QM + mloc];
            float2* po = reinterpret_cast<float2*>(op + (size_t)r * DIM);
            po[0] = make_float2(oa.x, oa.y);
            po[1] = make_float2(oa.z, oa.w);
            po[2] = ob;
        }

        // ---- Rotate prefetched registers in.
        #pragma unroll
        for (int r = 0; r < RPT; r++)
            #pragma unroll
            for (int d = 0; d < D_SUB; d++)
                xv[r][d] = nx[r][d];

        xp = nxp;
        op += step;
    }
}

extern "C" void kernel_launch(void* const* d_in, const int* in_sizes, int n_in,
                              void* d_out, int out_size)
{
    const float* x  = (const float*)d_in[0];
    const float* cb = (const float*)d_in[1];
    float* out      = (float*)d_out;

    pq_head_kernel<<<NBLOCKS, TPB>>>(x, cb, out);
}